// round 1
// baseline (speedup 1.0000x reference)
#include <cuda_runtime.h>
#include <math.h>
#include <stdint.h>

#define T_STEPS 32
#define NB      256
#define HID     64
#define G3      192      // 3*HID
#define OBS_LEN 128
#define SUB_OFF 128
#define ACT_OFF 146
#define IN_FEAT 147
#define STATE   78
#define GRU_IN  8384
#define CONV_COLS 8192
#define OBS_V   16
#define SUB_V   20
#define NSUB    6
#define SUBDIM  3

// ---------------- scratch (device globals; no allocations allowed) ----------
__device__ float d_Wt[CONV_COLS * G3];          // w_ih[:, :8192] transposed: [col][g]   6.3 MB
__device__ float d_E[128 * 2 * 16];             // E[o][d][v]
__device__ float d_R[3 * SUB_V * G3];           // R[j][v][g]
__device__ float d_Tab[128 * 16 * G3];          // Tab[pos][v][g]                        1.5 MB
__device__ float d_Tab2[64 * 256 * G3];         // Tab2[pairpos][v1*16+v2][g]           12.6 MB
__device__ float d_gxc[T_STEPS * NB * G3];      // precomputed conv-part of gx + b_ih    6.3 MB

// ---------------- K1: transpose first 8192 columns of w_ih ------------------
__global__ void k_transpose(const float* __restrict__ w_ih) {
    __shared__ float tile[32][33];
    int col = blockIdx.x * 32 + threadIdx.x;          // 0..8191
    int row = blockIdx.y * 32 + threadIdx.y;          // 0..191
    tile[threadIdx.y][threadIdx.x] = w_ih[(size_t)row * GRU_IN + col];
    __syncthreads();
    int ocol = blockIdx.x * 32 + threadIdx.y;
    int orow = blockIdx.y * 32 + threadIdx.x;
    d_Wt[(size_t)ocol * G3 + orow] = tile[threadIdx.x][threadIdx.y];
}

// ---------------- K2: small tables E (conv_w x obs_emb) and R (w_ih_r x sub_emb)
__global__ void k_er(const float* __restrict__ conv_w,
                     const float* __restrict__ obs_emb,
                     const float* __restrict__ w_ih,
                     const float* __restrict__ sub_emb) {
    int tid = blockIdx.x * 256 + threadIdx.x;
    if (tid < 128 * 2 * 16) {
        int v = tid & 15, d = (tid >> 4) & 1, o = tid >> 5;
        float a = 0.f;
        #pragma unroll 8
        for (int h = 0; h < HID; h++)
            a += conv_w[o * 128 + d * 64 + h] * obs_emb[v * HID + h];
        d_E[tid] = a;                                  // layout ((o*2+d)*16+v)
    } else if (tid < 128 * 2 * 16 + 3 * SUB_V * G3) {
        int r = tid - 128 * 2 * 16;
        int g = r % G3, v = (r / G3) % SUB_V, j = r / (G3 * SUB_V);
        float a = 0.f;
        #pragma unroll 8
        for (int h = 0; h < HID; h++)
            a += w_ih[(size_t)g * GRU_IN + CONV_COLS + j * 64 + h] * sub_emb[v * HID + h];
        d_R[r] = a;                                    // layout ((j*20+v)*192+g)
    }
}

// ---------------- K3: Tab[pos][v][g] = sum_o Wt[o*64+s][g]*E[o][d][v] + conv_b term
__global__ void __launch_bounds__(192) k_tab(const float* __restrict__ conv_b) {
    __shared__ float E_s[128 * 16];
    __shared__ float cb_s[128];
    int pos = blockIdx.x;                // 0..127,  pos = d*64 + s
    int d = pos >> 6, s = pos & 63;
    int g = threadIdx.x;
    for (int i = g; i < 2048; i += 192) {
        int o = i >> 4, v = i & 15;
        E_s[i] = d_E[(o * 2 + d) * 16 + v];
    }
    if (g < 128) cb_s[g] = conv_b[g];
    __syncthreads();
    float acc[16];
    #pragma unroll
    for (int v = 0; v < 16; v++) acc[v] = 0.f;
    float cacc = 0.f;
    for (int o = 0; o < 128; o++) {
        float w = d_Wt[(size_t)(o * 64 + s) * G3 + g];
        cacc += w * cb_s[o];
        #pragma unroll
        for (int v = 0; v < 16; v++) acc[v] += w * E_s[o * 16 + v];
    }
    #pragma unroll
    for (int v = 0; v < 16; v++)
        d_Tab[(size_t)(pos * 16 + v) * G3 + g] = acc[v] + cacc;
}

// ---------------- K4: pair table Tab2[pp][v1*16+v2][g] = Tab[2pp][v1][g]+Tab[2pp+1][v2][g]
__global__ void __launch_bounds__(192) k_tab2() {
    int pp = blockIdx.x;                 // 0..63
    int v1 = blockIdx.y;                 // 0..15
    int g  = threadIdx.x;
    float t1 = d_Tab[(size_t)((2 * pp) * 16 + v1) * G3 + g];
    const float* t2 = &d_Tab[(size_t)((2 * pp + 1) * 16) * G3 + g];
    float* out = &d_Tab2[(size_t)(pp * 256 + v1 * 16) * G3 + g];
    #pragma unroll
    for (int v2 = 0; v2 < 16; v2++)
        out[(size_t)v2 * G3] = t1 + t2[(size_t)v2 * G3];
}

// ---------------- K5: gather gx_conv for all (t,n) --------------------------
__global__ void __launch_bounds__(192) k_gxc(const float* __restrict__ inputs,
                                             const float* __restrict__ b_ih) {
    __shared__ int pv[64];
    int tn = blockIdx.x;                 // t*256+n
    int g = threadIdx.x;
    const float* row = inputs + (size_t)tn * IN_FEAT;
    if (g < 64) {
        int v1 = __float2int_rn(row[2 * g]);
        int v2 = __float2int_rn(row[2 * g + 1]);
        pv[g] = v1 * 16 + v2;
    }
    __syncthreads();
    float acc = b_ih[g];
    #pragma unroll 8
    for (int pp = 0; pp < 64; pp++)
        acc += d_Tab2[(size_t)((pp << 8) + pv[pp]) * G3 + g];
    d_gxc[(size_t)tn * G3 + g] = acc;
}

// ---------------- K6: the recurrence (one block per sample) -----------------
__global__ void __launch_bounds__(192) k_rec(
    const float* __restrict__ inputs, const float* __restrict__ hx,
    const float* __restrict__ w_hh, const float* __restrict__ b_hh,
    const float* __restrict__ critic_w, const float* __restrict__ critic_b,
    const float* __restrict__ phi_w, const float* __restrict__ phi_b,
    float* __restrict__ out)
{
    __shared__ float Q_s[NSUB][G3];
    __shared__ float A[G3], B[G3];
    __shared__ float h_s[HID], hn_s[HID];
    __shared__ float pc[HID], vc[HID];
    __shared__ float p_s[8];
    __shared__ float phi_s[HID], crit_s[HID], bhh_s[G3];
    __shared__ float scal[2];
    __shared__ int flag;

    int n = blockIdx.x;
    int g = threadIdx.x;

    float wreg[HID];
    #pragma unroll
    for (int h = 0; h < HID; h++) wreg[h] = w_hh[(size_t)g * HID + h];

    bhh_s[g] = b_hh[g];
    if (g < HID) { phi_s[g] = phi_w[g]; crit_s[g] = critic_w[g]; }

    // per-sample subtask matrix contribution Q[s][g] (uses t=0 sub indices)
    const float* in0 = inputs + (size_t)n * IN_FEAT;
    #pragma unroll
    for (int s = 0; s < NSUB; s++) {
        float q = 0.f;
        #pragma unroll
        for (int j = 0; j < SUBDIM; j++) {
            int v = __float2int_rn(in0[SUB_OFF + s * SUBDIM + j]);
            q += d_R[(size_t)(j * SUB_V + v) * G3 + g];
        }
        Q_s[s][g] = q;
    }

    if (g == 0) flag = 0;
    __syncthreads();
    if (g < STATE) { if (hx[(size_t)n * STATE + g] != 0.0f) atomicOr(&flag, 1); }
    if (g < HID) h_s[g] = hx[(size_t)n * STATE + 2 + g];
    __syncthreads();
    if (g == 0) {
        #pragma unroll
        for (int i = 0; i < NSUB; i++) p_s[i] = hx[(size_t)n * STATE + 72 + i];
        if (flag == 0) p_s[0] = 1.0f;   // new episode
    }
    __syncthreads();

    float phib = phi_b[0], critb = critic_b[0];
    float gxl = d_gxc[((size_t)0 * NB + n) * G3 + g];

    for (int t = 0; t < T_STEPS; t++) {
        // gx = precomputed conv part (+b_ih) + p . Q
        float gx = gxl;
        #pragma unroll
        for (int s = 0; s < NSUB; s++) gx += p_s[s] * Q_s[s][g];
        // gh = w_hh @ h + b_hh (weights in registers, h broadcast from smem)
        float gh = bhh_s[g];
        #pragma unroll
        for (int h4 = 0; h4 < HID / 4; h4++) {
            float4 hv = *reinterpret_cast<const float4*>(&h_s[h4 * 4]);
            gh += wreg[h4 * 4 + 0] * hv.x + wreg[h4 * 4 + 1] * hv.y
                + wreg[h4 * 4 + 2] * hv.z + wreg[h4 * 4 + 3] * hv.w;
        }
        A[g] = gx; B[g] = gh;
        if (t + 1 < T_STEPS)
            gxl = d_gxc[((size_t)(t + 1) * NB + n) * G3 + g];   // prefetch next step
        __syncthreads();

        if (g < HID) {
            float r  = 1.f / (1.f + expf(-(A[g] + B[g])));
            float z  = 1.f / (1.f + expf(-(A[g + 64] + B[g + 64])));
            float nn = tanhf(A[g + 128] + r * B[g + 128]);
            float hn = (1.f - z) * nn + z * h_s[g];
            hn_s[g] = hn;
            pc[g] = hn * phi_s[g];
            vc[g] = hn * crit_s[g];
            out[((size_t)t * NB + n) * STATE + 2 + g] = hn;
        }
        __syncthreads();

        if (g < 32) {                       // warp 0: phi head reduction -> c
            float x = pc[g] + pc[g + 32];
            #pragma unroll
            for (int m = 16; m > 0; m >>= 1) x += __shfl_xor_sync(0xffffffffu, x, m);
            if (g == 0) scal[0] = 1.f / (1.f + expf(-(x + phib)));
        } else if (g < 64) {                // warp 1: critic head reduction -> v
            int l = g - 32;
            float x = vc[l] + vc[l + 32];
            #pragma unroll
            for (int m = 16; m > 0; m >>= 1) x += __shfl_xor_sync(0xffffffffu, x, m);
            if (l == 0) scal[1] = x + critb;
        } else if (g < 128) {               // warps 2-3: commit h
            h_s[g - 64] = hn_s[g - 64];
        }
        __syncthreads();

        if (g == 0) {
            float c = scal[0], v = scal[1];
            size_t base = ((size_t)t * NB + n) * STATE;
            out[base]     = inputs[((size_t)t * NB + n) * IN_FEAT + ACT_OFF];  // action
            out[base + 1] = v;
            float pt = p_s[5];
            float pn[6]; float sum = 0.f;
            #pragma unroll
            for (int i = 0; i < 6; i++) {
                float p1 = (i == 0) ? 0.f : p_s[i - 1];
                float p2 = p1 + p_s[i] * pt;
                pn[i] = (1.f - c) * p_s[i] + c * p2;
                sum += pn[i];
            }
            float inv = 1.f / sum;
            #pragma unroll
            for (int i = 0; i < 6; i++) {
                out[base + 66 + i] = pn[i] * inv;   // probs
                out[base + 72 + i] = pn[i];         // p_new
                p_s[i] = pn[i];
            }
        }
        __syncthreads();
    }

    // second output: hx_out[-1:] appended after the (T,N,STATE) block
    if (g < STATE) {
        out[(size_t)T_STEPS * NB * STATE + (size_t)n * STATE + g] =
            out[((size_t)(T_STEPS - 1) * NB + n) * STATE + g];
    }
}

// ---------------- launcher ---------------------------------------------------
extern "C" void kernel_launch(void* const* d_in, const int* in_sizes, int n_in,
                              void* d_out, int out_size) {
    const float* inputs   = (const float*)d_in[0];
    const float* hx       = (const float*)d_in[1];
    const float* sub_emb  = (const float*)d_in[2];
    const float* obs_emb  = (const float*)d_in[3];
    const float* conv_w   = (const float*)d_in[4];
    const float* conv_b   = (const float*)d_in[5];
    const float* w_ih     = (const float*)d_in[6];
    const float* w_hh     = (const float*)d_in[7];
    const float* b_ih     = (const float*)d_in[8];
    const float* b_hh     = (const float*)d_in[9];
    const float* critic_w = (const float*)d_in[10];
    const float* critic_b = (const float*)d_in[11];
    const float* phi_w    = (const float*)d_in[12];
    const float* phi_b    = (const float*)d_in[13];
    float* out = (float*)d_out;

    k_transpose<<<dim3(CONV_COLS / 32, G3 / 32), dim3(32, 32)>>>(w_ih);
    k_er<<<(128 * 2 * 16 + 3 * SUB_V * G3 + 255) / 256, 256>>>(conv_w, obs_emb, w_ih, sub_emb);
    k_tab<<<128, 192>>>(conv_b);
    k_tab2<<<dim3(64, 16), 192>>>();
    k_gxc<<<T_STEPS * NB, 192>>>(inputs, b_ih);
    k_rec<<<NB, 192>>>(inputs, hx, w_hh, b_hh, critic_w, critic_b, phi_w, phi_b, out);
}

// round 2
// speedup vs baseline: 1.1592x; 1.1592x over previous
#include <cuda_runtime.h>
#include <cuda_fp16.h>
#include <math.h>
#include <stdint.h>

#define T_STEPS 32
#define NB      256
#define HID     64
#define G3      192      // 3*HID
#define OBS_LEN 128
#define SUB_OFF 128
#define ACT_OFF 146
#define IN_FEAT 147
#define STATE   78
#define GRU_IN  8384
#define CONV_COLS 8192
#define OBS_V   16
#define SUB_V   20
#define NSUB    6
#define SUBDIM  3

// ---------------- scratch (device globals; no allocations allowed) ----------
__device__ float   d_Wt[CONV_COLS * G3];        // w_ih[:, :8192] transposed: [col][g]  6.3 MB
__device__ float   d_E[128 * 2 * 16];           // E[o][d][v]
__device__ float   d_R[3 * SUB_V * G3];         // R[j][v][g]
__device__ __half2 d_Tab2h[64 * 256 * 96];      // Tab2[pp][v1*16+v2][g as half2]      6.3 MB
__device__ float   d_gxc[T_STEPS * NB * G3];    // precomputed conv-part of gx + b_ih  6.3 MB

// ---------------- K1: transpose first 8192 columns of w_ih ------------------
__global__ void k_transpose(const float* __restrict__ w_ih) {
    __shared__ float tile[32][33];
    int col = blockIdx.x * 32 + threadIdx.x;          // 0..8191
    int row = blockIdx.y * 32 + threadIdx.y;          // 0..191
    tile[threadIdx.y][threadIdx.x] = w_ih[(size_t)row * GRU_IN + col];
    __syncthreads();
    int ocol = blockIdx.x * 32 + threadIdx.y;
    int orow = blockIdx.y * 32 + threadIdx.x;
    d_Wt[(size_t)ocol * G3 + orow] = tile[threadIdx.x][threadIdx.y];
}

// ---------------- K2: small tables E (conv_w x obs_emb) and R (w_ih_r x sub_emb)
__global__ void k_er(const float* __restrict__ conv_w,
                     const float* __restrict__ obs_emb,
                     const float* __restrict__ w_ih,
                     const float* __restrict__ sub_emb) {
    int tid = blockIdx.x * 256 + threadIdx.x;
    if (tid < 128 * 2 * 16) {
        int v = tid & 15, d = (tid >> 4) & 1, o = tid >> 5;
        float a = 0.f;
        #pragma unroll 8
        for (int h = 0; h < HID; h++)
            a += conv_w[o * 128 + d * 64 + h] * obs_emb[v * HID + h];
        d_E[tid] = a;                                  // layout ((o*2+d)*16+v)
    } else if (tid < 128 * 2 * 16 + 3 * SUB_V * G3) {
        int r = tid - 128 * 2 * 16;
        int g = r % G3, v = (r / G3) % SUB_V, j = r / (G3 * SUB_V);
        float a = 0.f;
        #pragma unroll 8
        for (int h = 0; h < HID; h++)
            a += w_ih[(size_t)g * GRU_IN + CONV_COLS + j * 64 + h] * sub_emb[v * HID + h];
        d_R[r] = a;                                    // layout ((j*20+v)*192+g)
    }
}

// ---------------- K3: fused Tab build -> fp16 pair table --------------------
// For pair pp (positions 2pp, 2pp+1, same d):
//   a1[v][g] = sum_o Wt[o*64+s0][g]*E[o][d][v]   (+ conv_b term once, on d==0)
//   a2[v][g] = likewise for s1
//   Tab2h[pp][v1*16+v2][g] = half(a1[v1][g] + a2[v2][g])
__global__ void __launch_bounds__(192) k_tabs(const float* __restrict__ conv_b) {
    __shared__ float E_s[128 * 16];
    __shared__ float cb_s[128];
    __shared__ float s1[16][192];
    __shared__ float s2[16][192];
    int pp = blockIdx.x;                 // 0..63
    int pos0 = 2 * pp;
    int d  = pos0 >> 6;
    int s0 = pos0 & 63, sA = (pos0 + 1) & 63;
    int g = threadIdx.x;
    for (int i = g; i < 2048; i += 192) {
        int o = i >> 4, v = i & 15;
        E_s[i] = d_E[(o * 2 + d) * 16 + v];
    }
    if (g < 128) cb_s[g] = conv_b[g];
    __syncthreads();

    float a1[16], a2[16];
    #pragma unroll
    for (int v = 0; v < 16; v++) { a1[v] = 0.f; a2[v] = 0.f; }
    float c1 = 0.f, c2 = 0.f;
    for (int o = 0; o < 128; o++) {
        float w0 = d_Wt[(size_t)(o * 64 + s0) * G3 + g];
        float w1 = d_Wt[(size_t)(o * 64 + sA) * G3 + g];
        float cb = cb_s[o];
        c1 += w0 * cb; c2 += w1 * cb;
        #pragma unroll
        for (int v = 0; v < 16; v++) {
            float e = E_s[o * 16 + v];
            a1[v] += w0 * e;
            a2[v] += w1 * e;
        }
    }
    // conv_b contribution must be counted once per spatial position: only d==0
    if (d != 0) { c1 = 0.f; c2 = 0.f; }
    #pragma unroll
    for (int v = 0; v < 16; v++) { s1[v][g] = a1[v] + c1; s2[v][g] = a2[v] + c2; }
    __syncthreads();

    __half2* outp = d_Tab2h + (size_t)pp * 256 * 96;
    #pragma unroll 4
    for (int it = 0; it < 128; it++) {
        int lin = it * 192 + g;          // 0..24575
        int combo = lin / 96, gg = lin % 96;
        int v1 = combo >> 4, v2 = combo & 15;
        float x0 = s1[v1][2 * gg]     + s2[v2][2 * gg];
        float x1 = s1[v1][2 * gg + 1] + s2[v2][2 * gg + 1];
        outp[lin] = __floats2half2_rn(x0, x1);
    }
}

// ---------------- K4: gather gx_conv for all (t,n), fp16 table --------------
// 2 samples per block; 96 threads per sample, each handling a g-pair via half2.
__global__ void __launch_bounds__(192) k_gxc(const float* __restrict__ inputs,
                                             const float* __restrict__ b_ih) {
    __shared__ int pv[2][64];
    int pair = blockIdx.x;               // 0..4095
    int sub = threadIdx.x / 96;
    int gg  = threadIdx.x % 96;
    int tn  = pair * 2 + sub;
    if (threadIdx.x < 128) {
        int s  = threadIdx.x >> 6;
        int pp = threadIdx.x & 63;
        const float* row = inputs + (size_t)(pair * 2 + s) * IN_FEAT;
        int v1 = __float2int_rn(row[2 * pp]);
        int v2 = __float2int_rn(row[2 * pp + 1]);
        pv[s][pp] = v1 * 16 + v2;
    }
    __syncthreads();
    float2 b = reinterpret_cast<const float2*>(b_ih)[gg];
    float ax = b.x, ay = b.y;
    const int* pvr = pv[sub];
    #pragma unroll 8
    for (int pp = 0; pp < 64; pp++) {
        __half2 hv = d_Tab2h[(size_t)((pp << 8) + pvr[pp]) * 96 + gg];
        float2 f = __half22float2(hv);
        ax += f.x; ay += f.y;
    }
    reinterpret_cast<float2*>(d_gxc)[(size_t)tn * 96 + gg] = make_float2(ax, ay);
}

// ---------------- K5: the recurrence (one block per sample) -----------------
__global__ void __launch_bounds__(192) k_rec(
    const float* __restrict__ inputs, const float* __restrict__ hx,
    const float* __restrict__ w_hh, const float* __restrict__ b_hh,
    const float* __restrict__ critic_w, const float* __restrict__ critic_b,
    const float* __restrict__ phi_w, const float* __restrict__ phi_b,
    float* __restrict__ out)
{
    __shared__ float Q_s[NSUB][G3];
    __shared__ float A[G3], B[G3];
    __shared__ float h_s[HID];
    __shared__ float pc[HID], vc[HID];
    __shared__ float p_s[8];
    __shared__ float phi_s[HID], crit_s[HID], bhh_s[G3];
    __shared__ int flag;

    int n = blockIdx.x;
    int g = threadIdx.x;

    float wreg[HID];
    #pragma unroll
    for (int h = 0; h < HID; h++) wreg[h] = w_hh[(size_t)g * HID + h];

    bhh_s[g] = b_hh[g];
    if (g < HID) { phi_s[g] = phi_w[g]; crit_s[g] = critic_w[g]; }

    // per-sample subtask matrix contribution Q[s][g] (t=0 sub indices)
    const float* in0 = inputs + (size_t)n * IN_FEAT;
    #pragma unroll
    for (int s = 0; s < NSUB; s++) {
        float q = 0.f;
        #pragma unroll
        for (int j = 0; j < SUBDIM; j++) {
            int v = __float2int_rn(in0[SUB_OFF + s * SUBDIM + j]);
            q += d_R[(size_t)(j * SUB_V + v) * G3 + g];
        }
        Q_s[s][g] = q;
    }

    if (g == 0) flag = 0;
    __syncthreads();
    if (g < STATE) { if (hx[(size_t)n * STATE + g] != 0.0f) atomicOr(&flag, 1); }
    if (g < HID) h_s[g] = hx[(size_t)n * STATE + 2 + g];
    __syncthreads();
    if (g == 0) {
        #pragma unroll
        for (int i = 0; i < NSUB; i++) p_s[i] = hx[(size_t)n * STATE + 72 + i];
        if (flag == 0) p_s[0] = 1.0f;   // new episode
    }
    __syncthreads();

    float phib = phi_b[0], critb = critic_b[0];
    float gxl = d_gxc[((size_t)0 * NB + n) * G3 + g];

    for (int t = 0; t < T_STEPS; t++) {
        // gx = precomputed conv part (+b_ih) + p . Q
        float gx = gxl;
        #pragma unroll
        for (int s = 0; s < NSUB; s++) gx += p_s[s] * Q_s[s][g];
        // gh = w_hh @ h + b_hh : 4-way split accumulation
        float ac0 = 0.f, ac1 = 0.f, ac2 = 0.f, ac3 = 0.f;
        #pragma unroll
        for (int h = 0; h < HID; h += 4) {
            float4 hv = *reinterpret_cast<const float4*>(&h_s[h]);
            ac0 += wreg[h]     * hv.x;
            ac1 += wreg[h + 1] * hv.y;
            ac2 += wreg[h + 2] * hv.z;
            ac3 += wreg[h + 3] * hv.w;
        }
        float gh = bhh_s[g] + (ac0 + ac1) + (ac2 + ac3);
        A[g] = gx; B[g] = gh;
        if (t + 1 < T_STEPS)
            gxl = d_gxc[((size_t)(t + 1) * NB + n) * G3 + g];   // prefetch next step
        __syncthreads();                                        // sync 1

        if (g < HID) {
            float r  = 1.f / (1.f + expf(-(A[g] + B[g])));
            float z  = 1.f / (1.f + expf(-(A[g + 64] + B[g + 64])));
            float nn = tanhf(A[g + 128] + r * B[g + 128]);
            float hn = (1.f - z) * nn + z * h_s[g];
            h_s[g] = hn;                 // in-place: all gh reads happened pre-sync1
            pc[g] = hn * phi_s[g];
            vc[g] = hn * crit_s[g];
            out[((size_t)t * NB + n) * STATE + 2 + g] = hn;
        }
        __syncthreads();                                        // sync 2

        size_t base = ((size_t)t * NB + n) * STATE;
        if (g < 32) {                       // warp 0: phi head -> c, then p update
            float x = pc[g] + pc[g + 32];
            #pragma unroll
            for (int m = 16; m > 0; m >>= 1) x += __shfl_xor_sync(0xffffffffu, x, m);
            if (g == 0) {
                float c = 1.f / (1.f + expf(-(x + phib)));
                out[base] = inputs[((size_t)t * NB + n) * IN_FEAT + ACT_OFF];
                float pt = p_s[5];
                float pn[6]; float sum = 0.f;
                #pragma unroll
                for (int i = 0; i < 6; i++) {
                    float p1 = (i == 0) ? 0.f : p_s[i - 1];
                    float p2 = p1 + p_s[i] * pt;
                    pn[i] = (1.f - c) * p_s[i] + c * p2;
                    sum += pn[i];
                }
                float inv = 1.f / sum;
                #pragma unroll
                for (int i = 0; i < 6; i++) {
                    out[base + 66 + i] = pn[i] * inv;   // probs
                    out[base + 72 + i] = pn[i];         // p_new
                    p_s[i] = pn[i];
                }
            }
        } else if (g < 64) {                // warp 1: critic head -> v
            int l = g - 32;
            float x = vc[l] + vc[l + 32];
            #pragma unroll
            for (int m = 16; m > 0; m >>= 1) x += __shfl_xor_sync(0xffffffffu, x, m);
            if (l == 0) out[base + 1] = x + critb;
        }
        __syncthreads();                                        // sync 3
    }

    // second output: hx_out[-1:] appended after the (T,N,STATE) block
    if (g < STATE) {
        out[(size_t)T_STEPS * NB * STATE + (size_t)n * STATE + g] =
            out[((size_t)(T_STEPS - 1) * NB + n) * STATE + g];
    }
}

// ---------------- launcher ---------------------------------------------------
extern "C" void kernel_launch(void* const* d_in, const int* in_sizes, int n_in,
                              void* d_out, int out_size) {
    const float* inputs   = (const float*)d_in[0];
    const float* hx       = (const float*)d_in[1];
    const float* sub_emb  = (const float*)d_in[2];
    const float* obs_emb  = (const float*)d_in[3];
    const float* conv_w   = (const float*)d_in[4];
    const float* conv_b   = (const float*)d_in[5];
    const float* w_ih     = (const float*)d_in[6];
    const float* w_hh     = (const float*)d_in[7];
    const float* b_ih     = (const float*)d_in[8];
    const float* b_hh     = (const float*)d_in[9];
    const float* critic_w = (const float*)d_in[10];
    const float* critic_b = (const float*)d_in[11];
    const float* phi_w    = (const float*)d_in[12];
    const float* phi_b    = (const float*)d_in[13];
    float* out = (float*)d_out;

    k_transpose<<<dim3(CONV_COLS / 32, G3 / 32), dim3(32, 32)>>>(w_ih);
    k_er<<<(128 * 2 * 16 + 3 * SUB_V * G3 + 255) / 256, 256>>>(conv_w, obs_emb, w_ih, sub_emb);
    k_tabs<<<64, 192>>>(conv_b);
    k_gxc<<<T_STEPS * NB / 2, 192>>>(inputs, b_ih);
    k_rec<<<NB, 192>>>(inputs, hx, w_hh, b_hh, critic_w, critic_b, phi_w, phi_b, out);
}